// round 14
// baseline (speedup 1.0000x reference)
#include <cuda_runtime.h>
#include <stdint.h>

#define IMGD   192
#define PATCHD 96
#define PVOX   (PATCHD*PATCHD*PATCHD)         // 884736
#define VVOX   (IMGD*IMGD*IMGD)               // 7077888
#define K_PRE  1000
#define MAX_OUT 100
#define NBINS  65536
#define CAND_CAP 2048
#define STAGE_ROWS 256
#define SCORE_THR 0.01f
#define MIN_SIZE  0.01f
#define IOU_THR   0.1f
#define CLS_OFF   384.0f   // 2.0 * 192.0

// ---------------- device scratch (self-cleaning; no allocations allowed) ----------------
__device__ unsigned int       g_hist[NBINS];        // zero at load; re-zeroed by hist_thresh
__device__ unsigned int       g_done       = 0;     // re-zeroed by hist_thresh
__device__ unsigned int       g_cand_count = 0;     // reset by final_kernel
__device__ unsigned int       g_validmask[32];      // reset by final_kernel
__device__ int                g_thresh_bin;
__device__ unsigned long long g_cands[CAND_CAP];
__device__ float              g_box [K_PRE*6];
__device__ float              g_obox[K_PRE*6];
__device__ float              g_sc  [K_PRE];
__device__ int                g_lab [K_PRE];
__device__ unsigned int       g_sup [K_PRE*32];

__device__ __forceinline__ unsigned fkey(float f) {
    unsigned u = __float_as_uint(f);
    return (u & 0x80000000u) ? ~u : (u | 0x80000000u);
}

// ---------------- seg ensemble kernel (closed-form coverage, float4) ----------------
__global__ void seg_kernel(const float* __restrict__ tiles,
                           const float* __restrict__ w,
                           float* __restrict__ out,
                           int C) {
    int v4 = blockIdx.x * blockDim.x + threadIdx.x;   // float4-group index
    if (v4 >= VVOX / 4) return;
    int zq = v4 % (IMGD / 4);
    int t2 = v4 / (IMGD / 4);
    int y  = t2 % IMGD;
    int x  = t2 / IMGD;
    int z  = zq * 4;

    int ix = (x >= 96) ? 2 : ((x >= 48) ? 1 : 0);
    int iy = (y >= 96) ? 2 : ((y >= 48) ? 1 : 0);
    int iz = (z >= 96) ? 2 : ((z >= 48) ? 1 : 0);
    bool two_x = (x >= 48) && (x < 144);
    bool two_y = (y >= 48) && (y < 144);
    bool two_z = (z >= 48) && (z < 144);

    int lx = x - ix * 48, ly = y - iy * 48, lz = z - iz * 48;
    int li = (lx * PATCHD + ly) * PATCHD + lz;

    float4 ws = make_float4(0.f, 0.f, 0.f, 0.f);
    float4 wl = make_float4(0.f, 0.f, 0.f, 0.f);
    #pragma unroll
    for (int a = 0; a < 2; a++) {
        if (a == 1 && !two_x) break;
        int xx = lx + a * 48;
        #pragma unroll
        for (int b = 0; b < 2; b++) {
            if (b == 1 && !two_y) break;
            int yy = ly + b * 48;
            #pragma unroll
            for (int cdim = 0; cdim < 2; cdim++) {
                if (cdim == 1 && !two_z) break;
                int zz = lz + cdim * 48;
                float4 wv = *reinterpret_cast<const float4*>(
                    w + (xx * PATCHD + yy) * PATCHD + zz);
                ws.x += wv.x; ws.y += wv.y; ws.z += wv.z; ws.w += wv.w;
                if (a == 0 && b == 0 && cdim == 0) wl = wv;
            }
        }
    }

    int tlast = ix * 9 + iy * 3 + iz;
    int v = v4 * 4;
    float4 inv = make_float4(wl.x / ws.x, wl.y / ws.y, wl.z / ws.z, wl.w / ws.w);
    for (int c = 0; c < C; c++) {
        float4 tv = *reinterpret_cast<const float4*>(
            tiles + (size_t)(tlast * C + c) * PVOX + li);
        float4 o;
        o.x = tv.x * inv.x; o.y = tv.y * inv.y;
        o.z = tv.z * inv.z; o.w = tv.w * inv.w;
        *reinterpret_cast<float4*>(out + (size_t)c * VVOX + v) = o;
    }
}

// ---------------- fused histogram + threshold (last-block-done) + self-clean ----------------
__global__ void hist_thresh_kernel(const float* __restrict__ bb, int N) {
    int i = blockIdx.x * blockDim.x + threadIdx.x;
    if (i < N) {
        float s = __ldg(bb + (size_t)i * 7 + 6);
        atomicAdd(&g_hist[fkey(s) >> 16], 1u);
    }
    __threadfence();
    __syncthreads();
    __shared__ int slast;
    if (threadIdx.x == 0)
        slast = (atomicAdd(&g_done, 1u) == gridDim.x - 1) ? 1 : 0;
    __syncthreads();
    if (!slast) return;

    // last block: 256-thread suffix scan over 256 chunks of 256 bins
    __shared__ unsigned csum[256];
    int tid = threadIdx.x;
    unsigned s = 0;
    const uint4* hv = reinterpret_cast<const uint4*>(g_hist) + tid * 64;
    #pragma unroll
    for (int q = 0; q < 64; q++) {
        uint4 v = hv[q];
        s += v.x + v.y + v.z + v.w;
    }
    csum[tid] = s;
    __syncthreads();
    for (int off = 1; off < 256; off <<= 1) {
        unsigned v = (tid + off < 256) ? csum[tid + off] : 0u;
        __syncthreads();
        csum[tid] += v;
        __syncthreads();
    }
    if (csum[tid] >= K_PRE && (tid == 255 || csum[tid + 1] < K_PRE)) {
        unsigned acc = (tid == 255) ? 0u : csum[tid + 1];
        int base = tid * 256;
        int bin = base;
        for (int b = 255; b >= 0; b--) {
            acc += g_hist[base + b];
            if (acc >= K_PRE) { bin = base + b; break; }
        }
        g_thresh_bin = bin;
    }
    __syncthreads();
    // self-clean hist + done for next graph replay (only this block reads hist)
    uint4* hz = reinterpret_cast<uint4*>(g_hist) + tid * 64;
    uint4 zz = make_uint4(0u, 0u, 0u, 0u);
    #pragma unroll
    for (int q = 0; q < 64; q++) hz[q] = zz;
    if (tid == 0) g_done = 0;
}

__global__ void gather_kernel(const float* __restrict__ bb, int N) {
    int i = blockIdx.x * blockDim.x + threadIdx.x;
    if (i >= N) return;
    float s = __ldg(bb + (size_t)i * 7 + 6);
    unsigned key = fkey(s);
    if ((int)(key >> 16) >= g_thresh_bin) {
        unsigned pos = atomicAdd(&g_cand_count, 1u);
        if (pos < CAND_CAP)
            g_cands[pos] = ((unsigned long long)key << 32) | (unsigned)(~(unsigned)i);
    }
}

// ---------------- rank by counting + prep (one warp per candidate, smem-staged) ----------------
__global__ void rank_kernel(const float* __restrict__ bb,
                            const int* __restrict__ labels) {
    __shared__ unsigned long long sc_[CAND_CAP];
    unsigned count = g_cand_count;
    if (count > CAND_CAP) count = CAND_CAP;
    for (int k = threadIdx.x; k < (int)count; k += blockDim.x)
        sc_[k] = g_cands[k];
    __syncthreads();

    int gw   = (blockIdx.x * blockDim.x + threadIdx.x) >> 5;
    int lane = threadIdx.x & 31;
    if (gw >= (int)count) return;

    unsigned long long key = sc_[gw];
    int r = 0;
    for (int k = lane; k < (int)count; k += 32)
        r += (sc_[k] > key) ? 1 : 0;
    #pragma unroll
    for (int o = 16; o > 0; o >>= 1) r += __shfl_down_sync(0xffffffffu, r, o);
    r = __shfl_sync(0xffffffffu, r, 0);
    if (r >= K_PRE) return;

    if (lane == 0) {
        unsigned idx = ~((unsigned)key);
        const float* p = bb + (size_t)idx * 7;
        float sc = __ldg(p + 6);
        int lb = __ldg(labels + idx);
        float off = (float)lb * CLS_OFF;
        bool valid = sc > SCORE_THR;
        #pragma unroll
        for (int d = 0; d < 3; d++) {
            float lo = fminf(fmaxf(__ldg(p + d),     0.0f), (float)IMGD);
            float hi = fminf(fmaxf(__ldg(p + d + 3), 0.0f), (float)IMGD);
            g_box [r*6 + d]     = lo;
            g_box [r*6 + d + 3] = hi;
            g_obox[r*6 + d]     = lo + off;
            g_obox[r*6 + d + 3] = hi + off;
            valid = valid && ((hi - lo) >= MIN_SIZE);
        }
        g_sc[r] = sc;
        g_lab[r] = lb;
        if (valid) atomicOr(&g_validmask[r >> 5], 1u << (r & 31));
    }
}

// ---------------- suppression bitmask (one block per row, ballot, no smem) ----------------
__global__ void sup_kernel() {
    int i = blockIdx.x;                 // row 0..K_PRE-1
    int wrp = threadIdx.x >> 5;         // 0..7
    int lane = threadIdx.x & 31;

    float a0 = __ldg(&g_obox[i*6+0]), a1 = __ldg(&g_obox[i*6+1]), a2 = __ldg(&g_obox[i*6+2]);
    float a3 = __ldg(&g_obox[i*6+3]), a4 = __ldg(&g_obox[i*6+4]), a5 = __ldg(&g_obox[i*6+5]);
    float va = ((a3 - a0) * (a4 - a1)) * (a5 - a2);

    #pragma unroll
    for (int wq = 0; wq < 4; wq++) {
        int word = wrp + wq * 8;        // 0..31
        int j = word * 32 + lane;
        bool sup = false;
        if (j < K_PRE && j > i) {
            float b0 = __ldg(&g_obox[j*6+0]), b1 = __ldg(&g_obox[j*6+1]), b2 = __ldg(&g_obox[j*6+2]);
            float b3 = __ldg(&g_obox[j*6+3]), b4 = __ldg(&g_obox[j*6+4]), b5 = __ldg(&g_obox[j*6+5]);
            float cx = fmaxf(fminf(a3, b3) - fmaxf(a0, b0), 0.0f);
            float cy = fmaxf(fminf(a4, b4) - fmaxf(a1, b1), 0.0f);
            float cz = fmaxf(fminf(a5, b5) - fmaxf(a2, b2), 0.0f);
            float inter = (cx * cy) * cz;
            float vb = ((b3 - b0) * (b4 - b1)) * (b5 - b2);
            float uni = fmaxf(va + vb - inter, 1e-6f);
            sup = (inter / uni > IOU_THR);
        }
        unsigned m = __ballot_sync(0xffffffffu, sup);
        if (lane == 0) g_sup[i*32 + word] = m;
    }
}

// ---------------- final: stage, 1-warp scan, emit, then self-clean state ----------------
__global__ void final_kernel(float* __restrict__ dets,   // [100,8]
                             float* __restrict__ labs) { // [100]
    __shared__ unsigned ssup[STAGE_ROWS * 32];  // 32 KB static
    __shared__ int kept[MAX_OUT];
    int tid = threadIdx.x;
    for (int i = tid; i < STAGE_ROWS * 32; i += blockDim.x)
        ssup[i] = g_sup[i];
    __syncthreads();

    if (tid < 32) {
        int lane = tid;
        unsigned keepw = g_validmask[lane];
        int nk = 0;
        for (int i = 0; i < K_PRE; i++) {
            unsigned w = __shfl_sync(0xffffffffu, keepw, i >> 5);
            if ((w >> (i & 31)) & 1u) {
                if (lane == 0) kept[nk] = i;
                nk++;
                if (nk == MAX_OUT) break;
                unsigned srow = (i < STAGE_ROWS) ? ssup[i*32 + lane] : g_sup[i*32 + lane];
                keepw &= ~srow;
            }
        }
        __syncwarp();
        for (int r = lane; r < MAX_OUT; r += 32) {
            if (r < nk) {
                int i = kept[r];
                #pragma unroll
                for (int d = 0; d < 6; d++) dets[r*8 + d] = g_box[i*6 + d];
                float s = g_sc[i];
                dets[r*8 + 6] = s;
                dets[r*8 + 7] = s;
                labs[r] = (float)g_lab[i];
            } else {
                #pragma unroll
                for (int d = 0; d < 8; d++) dets[r*8 + d] = 0.0f;
                labs[r] = -1.0f;
            }
        }
        // self-clean (after all reads of validmask)
        g_validmask[lane] = 0u;
    }
    if (tid == 32) {
        g_cand_count = 0u;
    }
}

// ---------------- launch (single stream, graph-capture safe, 6 nodes) ----------------
extern "C" void kernel_launch(void* const* d_in, const int* in_sizes, int n_in,
                              void* d_out, int out_size) {
    const float* tiles  = (const float*)d_in[0];
    const float* w      = (const float*)d_in[1];
    const float* bb     = (const float*)d_in[2];
    const int*   labels = (const int*)  d_in[3];

    int T = in_sizes[4] / 3;
    int C = in_sizes[0] / (T * PVOX);
    int N = in_sizes[2] / 7;
    float* out = (float*)d_out;

    size_t seg_elems = (size_t)C * VVOX;

    hist_thresh_kernel<<<(N + 255) / 256, 256>>>(bb, N);
    gather_kernel<<<(N + 255) / 256, 256>>>(bb, N);
    rank_kernel<<<(CAND_CAP * 32 + 1023) / 1024, 1024>>>(bb, labels);
    sup_kernel<<<K_PRE, 256>>>();
    final_kernel<<<1, 1024>>>(out + seg_elems, out + seg_elems + MAX_OUT * 8);

    seg_kernel<<<(VVOX / 4 + 255) / 256, 256>>>(tiles, w, out, C);
}

// round 17
// speedup vs baseline: 1.1060x; 1.1060x over previous
#include <cuda_runtime.h>
#include <stdint.h>

#define IMGD   192
#define PATCHD 96
#define PVOX   (PATCHD*PATCHD*PATCHD)         // 884736
#define VVOX   (IMGD*IMGD*IMGD)               // 7077888
#define K_PRE  1000
#define MAX_OUT 100
#define NBINS  65536
#define CAND_CAP 2048
#define STAGE_ROWS 256
#define SCORE_THR 0.01f
#define MIN_SIZE  0.01f
#define IOU_THR   0.1f
#define CLS_OFF   384.0f   // 2.0 * 192.0

// ---------------- device scratch (self-cleaning; no allocations allowed) ----------------
__device__ unsigned int       g_hist[NBINS];        // zero at load; re-zeroed by seg_kernel
__device__ unsigned int       g_done       = 0;     // reset by final_kernel
__device__ unsigned int       g_cand_count = 0;     // reset by final_kernel
__device__ unsigned int       g_validmask[32];      // reset by final_kernel
__device__ int                g_thresh_bin;         // overwritten each run
__device__ unsigned long long g_cands[CAND_CAP];
__device__ float              g_box [K_PRE*6];
__device__ float              g_obox[K_PRE*6];
__device__ float              g_sc  [K_PRE];
__device__ int                g_lab [K_PRE];
__device__ unsigned int       g_sup [K_PRE*32];

__device__ __forceinline__ unsigned fkey(float f) {
    unsigned u = __float_as_uint(f);
    return (u & 0x80000000u) ? ~u : (u | 0x80000000u);
}

// ---------------- seg ensemble kernel (closed-form coverage, float4) ----------------
// Blocks 0..255 additionally zero the 64K-entry histogram (1 word/thread) for
// the NEXT graph replay — fully parallel, hidden under seg's memory traffic.
__global__ void seg_kernel(const float* __restrict__ tiles,
                           const float* __restrict__ w,
                           float* __restrict__ out,
                           int C) {
    if (blockIdx.x < NBINS / 256)
        g_hist[blockIdx.x * 256 + threadIdx.x] = 0u;

    int v4 = blockIdx.x * blockDim.x + threadIdx.x;   // float4-group index
    if (v4 >= VVOX / 4) return;
    int zq = v4 % (IMGD / 4);
    int t2 = v4 / (IMGD / 4);
    int y  = t2 % IMGD;
    int x  = t2 / IMGD;
    int z  = zq * 4;

    int ix = (x >= 96) ? 2 : ((x >= 48) ? 1 : 0);
    int iy = (y >= 96) ? 2 : ((y >= 48) ? 1 : 0);
    int iz = (z >= 96) ? 2 : ((z >= 48) ? 1 : 0);
    bool two_x = (x >= 48) && (x < 144);
    bool two_y = (y >= 48) && (y < 144);
    bool two_z = (z >= 48) && (z < 144);

    int lx = x - ix * 48, ly = y - iy * 48, lz = z - iz * 48;
    int li = (lx * PATCHD + ly) * PATCHD + lz;

    float4 ws = make_float4(0.f, 0.f, 0.f, 0.f);
    float4 wl = make_float4(0.f, 0.f, 0.f, 0.f);
    #pragma unroll
    for (int a = 0; a < 2; a++) {
        if (a == 1 && !two_x) break;
        int xx = lx + a * 48;
        #pragma unroll
        for (int b = 0; b < 2; b++) {
            if (b == 1 && !two_y) break;
            int yy = ly + b * 48;
            #pragma unroll
            for (int cdim = 0; cdim < 2; cdim++) {
                if (cdim == 1 && !two_z) break;
                int zz = lz + cdim * 48;
                float4 wv = *reinterpret_cast<const float4*>(
                    w + (xx * PATCHD + yy) * PATCHD + zz);
                ws.x += wv.x; ws.y += wv.y; ws.z += wv.z; ws.w += wv.w;
                if (a == 0 && b == 0 && cdim == 0) wl = wv;
            }
        }
    }

    int tlast = ix * 9 + iy * 3 + iz;
    int v = v4 * 4;
    float4 inv = make_float4(wl.x / ws.x, wl.y / ws.y, wl.z / ws.z, wl.w / ws.w);
    for (int c = 0; c < C; c++) {
        float4 tv = *reinterpret_cast<const float4*>(
            tiles + (size_t)(tlast * C + c) * PVOX + li);
        float4 o;
        o.x = tv.x * inv.x; o.y = tv.y * inv.y;
        o.z = tv.z * inv.z; o.w = tv.w * inv.w;
        *reinterpret_cast<float4*>(out + (size_t)c * VVOX + v) = o;
    }
}

// ---------------- fused histogram + threshold (last-block-done) ----------------
__global__ void hist_thresh_kernel(const float* __restrict__ bb, int N) {
    int i = blockIdx.x * blockDim.x + threadIdx.x;
    if (i < N) {
        float s = __ldg(bb + (size_t)i * 7 + 6);
        atomicAdd(&g_hist[fkey(s) >> 16], 1u);
    }
    __threadfence();
    __syncthreads();
    __shared__ int slast;
    if (threadIdx.x == 0)
        slast = (atomicAdd(&g_done, 1u) == gridDim.x - 1) ? 1 : 0;
    __syncthreads();
    if (!slast) return;

    // last block: 256-thread suffix scan over 256 chunks of 256 bins
    __shared__ unsigned csum[256];
    int tid = threadIdx.x;
    unsigned s = 0;
    const uint4* hv = reinterpret_cast<const uint4*>(g_hist) + tid * 64;
    #pragma unroll
    for (int q = 0; q < 64; q++) {
        uint4 v = hv[q];
        s += v.x + v.y + v.z + v.w;
    }
    csum[tid] = s;
    __syncthreads();
    for (int off = 1; off < 256; off <<= 1) {
        unsigned v = (tid + off < 256) ? csum[tid + off] : 0u;
        __syncthreads();
        csum[tid] += v;
        __syncthreads();
    }
    if (csum[tid] >= K_PRE && (tid == 255 || csum[tid + 1] < K_PRE)) {
        unsigned acc = (tid == 255) ? 0u : csum[tid + 1];
        int base = tid * 256;
        int bin = base;
        for (int b = 255; b >= 0; b--) {
            acc += g_hist[base + b];
            if (acc >= K_PRE) { bin = base + b; break; }
        }
        g_thresh_bin = bin;
    }
}

__global__ void gather_kernel(const float* __restrict__ bb, int N) {
    int i = blockIdx.x * blockDim.x + threadIdx.x;
    if (i >= N) return;
    float s = __ldg(bb + (size_t)i * 7 + 6);
    unsigned key = fkey(s);
    if ((int)(key >> 16) >= g_thresh_bin) {
        unsigned pos = atomicAdd(&g_cand_count, 1u);
        if (pos < CAND_CAP)
            g_cands[pos] = ((unsigned long long)key << 32) | (unsigned)(~(unsigned)i);
    }
}

// ---------------- rank by counting + prep (one warp per candidate, smem-staged) ----------------
__global__ void rank_kernel(const float* __restrict__ bb,
                            const int* __restrict__ labels) {
    __shared__ unsigned long long sc_[CAND_CAP];
    unsigned count = g_cand_count;
    if (count > CAND_CAP) count = CAND_CAP;
    for (int k = threadIdx.x; k < (int)count; k += blockDim.x)
        sc_[k] = g_cands[k];
    __syncthreads();

    int gw   = (blockIdx.x * blockDim.x + threadIdx.x) >> 5;
    int lane = threadIdx.x & 31;
    if (gw >= (int)count) return;

    unsigned long long key = sc_[gw];
    int r = 0;
    for (int k = lane; k < (int)count; k += 32)
        r += (sc_[k] > key) ? 1 : 0;
    #pragma unroll
    for (int o = 16; o > 0; o >>= 1) r += __shfl_down_sync(0xffffffffu, r, o);
    r = __shfl_sync(0xffffffffu, r, 0);
    if (r >= K_PRE) return;

    if (lane == 0) {
        unsigned idx = ~((unsigned)key);
        const float* p = bb + (size_t)idx * 7;
        float sc = __ldg(p + 6);
        int lb = __ldg(labels + idx);
        float off = (float)lb * CLS_OFF;
        bool valid = sc > SCORE_THR;
        #pragma unroll
        for (int d = 0; d < 3; d++) {
            float lo = fminf(fmaxf(__ldg(p + d),     0.0f), (float)IMGD);
            float hi = fminf(fmaxf(__ldg(p + d + 3), 0.0f), (float)IMGD);
            g_box [r*6 + d]     = lo;
            g_box [r*6 + d + 3] = hi;
            g_obox[r*6 + d]     = lo + off;
            g_obox[r*6 + d + 3] = hi + off;
            valid = valid && ((hi - lo) >= MIN_SIZE);
        }
        g_sc[r] = sc;
        g_lab[r] = lb;
        if (valid) atomicOr(&g_validmask[r >> 5], 1u << (r & 31));
    }
}

// ---------------- suppression bitmask (one block per row, ballot, no smem) ----------------
__global__ void sup_kernel() {
    int i = blockIdx.x;                 // row 0..K_PRE-1
    int wrp = threadIdx.x >> 5;         // 0..7
    int lane = threadIdx.x & 31;

    float a0 = __ldg(&g_obox[i*6+0]), a1 = __ldg(&g_obox[i*6+1]), a2 = __ldg(&g_obox[i*6+2]);
    float a3 = __ldg(&g_obox[i*6+3]), a4 = __ldg(&g_obox[i*6+4]), a5 = __ldg(&g_obox[i*6+5]);
    float va = ((a3 - a0) * (a4 - a1)) * (a5 - a2);

    #pragma unroll
    for (int wq = 0; wq < 4; wq++) {
        int word = wrp + wq * 8;        // 0..31
        int j = word * 32 + lane;
        bool sup = false;
        if (j < K_PRE && j > i) {
            float b0 = __ldg(&g_obox[j*6+0]), b1 = __ldg(&g_obox[j*6+1]), b2 = __ldg(&g_obox[j*6+2]);
            float b3 = __ldg(&g_obox[j*6+3]), b4 = __ldg(&g_obox[j*6+4]), b5 = __ldg(&g_obox[j*6+5]);
            float cx = fmaxf(fminf(a3, b3) - fmaxf(a0, b0), 0.0f);
            float cy = fmaxf(fminf(a4, b4) - fmaxf(a1, b1), 0.0f);
            float cz = fmaxf(fminf(a5, b5) - fmaxf(a2, b2), 0.0f);
            float inter = (cx * cy) * cz;
            float vb = ((b3 - b0) * (b4 - b1)) * (b5 - b2);
            float uni = fmaxf(va + vb - inter, 1e-6f);
            sup = (inter / uni > IOU_THR);
        }
        unsigned m = __ballot_sync(0xffffffffu, sup);
        if (lane == 0) g_sup[i*32 + word] = m;
    }
}

// ---------------- final: stage, 1-warp scan, emit, then reset counters ----------------
__global__ void final_kernel(float* __restrict__ dets,   // [100,8]
                             float* __restrict__ labs) { // [100]
    __shared__ unsigned ssup[STAGE_ROWS * 32];  // 32 KB static
    __shared__ int kept[MAX_OUT];
    int tid = threadIdx.x;
    for (int i = tid; i < STAGE_ROWS * 32; i += blockDim.x)
        ssup[i] = g_sup[i];
    __syncthreads();

    if (tid < 32) {
        int lane = tid;
        unsigned keepw = g_validmask[lane];
        int nk = 0;
        for (int i = 0; i < K_PRE; i++) {
            unsigned w = __shfl_sync(0xffffffffu, keepw, i >> 5);
            if ((w >> (i & 31)) & 1u) {
                if (lane == 0) kept[nk] = i;
                nk++;
                if (nk == MAX_OUT) break;
                unsigned srow = (i < STAGE_ROWS) ? ssup[i*32 + lane] : g_sup[i*32 + lane];
                keepw &= ~srow;
            }
        }
        __syncwarp();
        for (int r = lane; r < MAX_OUT; r += 32) {
            if (r < nk) {
                int i = kept[r];
                #pragma unroll
                for (int d = 0; d < 6; d++) dets[r*8 + d] = g_box[i*6 + d];
                float s = g_sc[i];
                dets[r*8 + 6] = s;
                dets[r*8 + 7] = s;
                labs[r] = (float)g_lab[i];
            } else {
                #pragma unroll
                for (int d = 0; d < 8; d++) dets[r*8 + d] = 0.0f;
                labs[r] = -1.0f;
            }
        }
        // self-clean validmask (after all reads)
        g_validmask[lane] = 0u;
    }
    if (tid == 32) g_cand_count = 0u;
    if (tid == 33) g_done = 0u;
}

// ---------------- launch (single stream, graph-capture safe, 6 nodes) ----------------
extern "C" void kernel_launch(void* const* d_in, const int* in_sizes, int n_in,
                              void* d_out, int out_size) {
    const float* tiles  = (const float*)d_in[0];
    const float* w      = (const float*)d_in[1];
    const float* bb     = (const float*)d_in[2];
    const int*   labels = (const int*)  d_in[3];

    int T = in_sizes[4] / 3;
    int C = in_sizes[0] / (T * PVOX);
    int N = in_sizes[2] / 7;
    float* out = (float*)d_out;

    size_t seg_elems = (size_t)C * VVOX;

    hist_thresh_kernel<<<(N + 255) / 256, 256>>>(bb, N);
    gather_kernel<<<(N + 255) / 256, 256>>>(bb, N);
    rank_kernel<<<(CAND_CAP * 32 + 1023) / 1024, 1024>>>(bb, labels);
    sup_kernel<<<K_PRE, 256>>>();
    final_kernel<<<1, 1024>>>(out + seg_elems, out + seg_elems + MAX_OUT * 8);

    seg_kernel<<<(VVOX / 4 + 255) / 256, 256>>>(tiles, w, out, C);
}